// round 17
// baseline (speedup 1.0000x reference)
#include <cuda_runtime.h>
#include <cuda_fp16.h>
#include <cuda_bf16.h>
#include <math.h>
#include <stdint.h>

// ---------------- problem constants ----------------
#define Bz   2
#define Sz   2048
#define Dz   2048
#define Hz   16
#define HDz  128
#define RNz  32
#define FFz  4096
#define WINz 256
#define TOK  (Bz*Sz)          // 4096 tokens
#define EPSF 1e-5f
#define SCALEF 0.08838834764831845f   // 1/sqrt(128)

// ---------------- scratch (device globals; no allocation allowed) ----------------
__device__ __half  g_nx  [TOK*Dz];      // fp16 LN output (attn branch)
__device__ __half  g_f   [TOK*Dz];      // fp16 LN output (ffn branch)
__device__ float   g_qkv [TOK*3*Dz];    // fp32; q,k tf32-rounded after qkrope; v raw
__device__ __half  g_y   [TOK*Dz];      // fp16 attention output
__device__ float   g_h   [TOK*Dz];      // fp32 residual stream (x + attn_out)
__device__ __half  g_ffn [TOK*FFz];     // fp16 gelu(f@w1+b1)
__device__ float   g_ffo [TOK*Dz];      // fp32 ffn tower output (pre-residual)
// fp16 weights, k-pair-interleaved: Wh[kp][n] = half2(W[2kp][n], W[2kp+1][n])
__device__ __half2 g_wqkvH[(Dz/2)*3*Dz];
__device__ __half2 g_woH  [(Dz/2)*Dz];
__device__ __half2 g_w1H  [(Dz/2)*FFz];
__device__ __half2 g_w2H  [(FFz/2)*Dz];

// ======================= helpers =======================
__device__ __forceinline__ uint32_t smem_u32(const void* p) {
    uint32_t a;
    asm("{ .reg .u64 t; cvta.to.shared.u64 t, %1; cvt.u32.u64 %0, t; }" : "=r"(a) : "l"(p));
    return a;
}
#define CP_ASYNC16(smem, gptr) \
    asm volatile("cp.async.cg.shared.global [%0], [%1], 16;" :: "r"(smem), "l"(gptr))
#define CP_COMMIT()  asm volatile("cp.async.commit_group;" ::: "memory")
#define CP_WAIT0()   asm volatile("cp.async.wait_group 0;" ::: "memory")
#define CP_WAIT1()   asm volatile("cp.async.wait_group 1;" ::: "memory")
#define CP_WAIT2()   asm volatile("cp.async.wait_group 2;" ::: "memory")

__device__ __forceinline__ uint32_t f2tf32(float x) {
    uint32_t r;
    asm("cvt.rna.tf32.f32 %0, %1;" : "=r"(r) : "f"(x));
    return r;
}
__device__ __forceinline__ float tf32v(float x) {
    return __uint_as_float(f2tf32(x));
}
// tf32 mma (attention only)
__device__ __forceinline__ void mma_tf32(float& c0, float& c1, float& c2, float& c3,
                                         uint32_t a0, uint32_t a1, uint32_t a2, uint32_t a3,
                                         uint32_t b0, uint32_t b1) {
    asm volatile(
        "mma.sync.aligned.m16n8k8.row.col.f32.tf32.tf32.f32 "
        "{%0,%1,%2,%3}, {%4,%5,%6,%7}, {%8,%9}, {%0,%1,%2,%3};"
        : "+f"(c0), "+f"(c1), "+f"(c2), "+f"(c3)
        : "r"(a0), "r"(a1), "r"(a2), "r"(a3), "r"(b0), "r"(b1));
}
// fp16 mma (GEMMs)
__device__ __forceinline__ void mma_f16(float& c0, float& c1, float& c2, float& c3,
                                        uint32_t a0, uint32_t a1, uint32_t a2, uint32_t a3,
                                        uint32_t b0, uint32_t b1) {
    asm volatile(
        "mma.sync.aligned.m16n8k16.row.col.f32.f16.f16.f32 "
        "{%0,%1,%2,%3}, {%4,%5,%6,%7}, {%8,%9}, {%0,%1,%2,%3};"
        : "+f"(c0), "+f"(c1), "+f"(c2), "+f"(c3)
        : "r"(a0), "r"(a1), "r"(a2), "r"(a3), "r"(b0), "r"(b1));
}

// ======================= merged weight fp16 pack (all 4 weights, one launch) =======================
// Wh[kp][n] = half2(W[2kp][n], W[2kp+1][n]); flat index j over [K/2 * N); base = 2j - n.
#define WE0 (1024*6144)     // wqkv
#define WE1 (1024*2048)     // wo
#define WE2 (1024*4096)     // w1
#define WE3 (2048*2048)     // w2
__global__ void wconv_all_kernel(const float* __restrict__ w0, const float* __restrict__ w1,
                                 const float* __restrict__ w2, const float* __restrict__ w3,
                                 __half2* __restrict__ o0, __half2* __restrict__ o1,
                                 __half2* __restrict__ o2, __half2* __restrict__ o3)
{
    const int total = WE0 + WE1 + WE2 + WE3;
    int i = blockIdx.x * 256 + threadIdx.x;
    const int stride = gridDim.x * 256;
    for (; i < total; i += stride) {
        const float* W; __half2* O; int j, N;
        if (i < WE0)                   { W = w0; O = o0; j = i;                 N = 6144; }
        else if (i < WE0 + WE1)        { W = w1; O = o1; j = i - WE0;           N = 2048; }
        else if (i < WE0 + WE1 + WE2)  { W = w2; O = o2; j = i - WE0 - WE1;     N = 4096; }
        else                           { W = w3; O = o3; j = i - WE0 - WE1 - WE2; N = 2048; }
        int n = j % N;
        size_t base = 2 * (size_t)j - n;
        O[j] = __floats2half2_rn(W[base], W[base + N]);
    }
}

// ======================= final residual join: out = a + b =======================
__global__ void add_kernel(const float* __restrict__ a, const float* __restrict__ b,
                           float* __restrict__ o) {
    int i = blockIdx.x * 256 + threadIdx.x;
    float4 va = ((const float4*)a)[i];
    float4 vb = ((const float4*)b)[i];
    ((float4*)o)[i] = make_float4(va.x + vb.x, va.y + vb.y, va.z + vb.z, va.w + vb.w);
}

// ======================= fp16 mma.sync GEMM =======================
// C[M,N] = A[M,K] @ W[K,N]  (+bias fp32, +gelu?, +res fp32?, out fp32 or fp16)
// A fp16 [M,K]; W pre-packed half2 [K/2,N].
// CTA 128x128, 256 threads = 8 warps (2x4), warp tile 64x32, BK=32, 3-stage cp.async.
// launch_bounds(256,2) caps regs at 128 -> 16 warps/SM (vs 8 before): latency hiding.
#define BM 128
#define BN 128
#define BK 32
#define AE 20                            // A row stride, half2 entries (bank perm 20*gid+tig)
#define BE 132                           // B row stride, half2 entries (bank perm 4*tig+gid)
#define A_ENT (BM * AE)                  // 2560
#define B_ENT (16 * BE)                  // 2112
#define STG_ENT (A_ENT + B_ENT)          // 4672 entries = 18688 B
#define STAGES 3
#define SM_TOTAL (STAGES * STG_ENT * 4)  // 56064 bytes

__global__ __launch_bounds__(256, 2)
void tc_gemm_kernel(const __half* __restrict__ A, const __half2* __restrict__ Wh,
                    const float* __restrict__ bias, const float* __restrict__ res,
                    void* __restrict__ Cv, int M, int N, int K, int do_gelu, int out_half)
{
    extern __shared__ uint32_t smem[];
    const uint32_t sm0 = smem_u32(smem);
    const int tid  = threadIdx.x;
    const int wid  = tid >> 5;
    const int lane = tid & 31;
    const int gid  = lane >> 2;
    const int tig  = lane & 3;
    const int wm   = wid >> 2;          // 0..1: 64-row slab
    const int wn   = wid & 3;           // 0..3: 32-col slab
    const int row0 = blockIdx.y * BM;
    const int col0 = blockIdx.x * BN;

    float acc[4][4][4];
    #pragma unroll
    for (int mi = 0; mi < 4; mi++)
        #pragma unroll
        for (int ni = 0; ni < 4; ni++)
            #pragma unroll
            for (int e = 0; e < 4; e++) acc[mi][ni][e] = 0.f;

    const int niter = K >> 5;

    // loader: 1024 16B-chunks per stage (512 A + 512 B), 4 per thread
    auto load_stage = [&](int buf, int iter) {
        const int k0  = iter << 5;      // halves
        const int kp0 = iter << 4;      // half2 k-pair rows
        const uint32_t sb = sm0 + (uint32_t)buf * (STG_ENT * 4);
        #pragma unroll
        for (int t = 0; t < 4; t++) {
            int c = tid + t * 256;
            const void* g;
            uint32_t s;
            if (c < 512) {                        // A: 128 rows x 4 chunks (32 halves/row)
                int row = c >> 2, ch = c & 3;
                g = A + (size_t)(row0 + row) * K + k0 + ch * 8;
                s = sb + (uint32_t)(row * 80 + ch * 16);
            } else {                              // B: 16 kp-rows x 32 chunks (128 half2/row)
                int cc = c - 512;
                int row = cc >> 5, c4 = cc & 31;
                g = Wh + (size_t)(kp0 + row) * N + col0 + c4 * 4;
                s = sb + (uint32_t)(A_ENT * 4 + row * 528 + c4 * 16);
            }
            CP_ASYNC16(s, g);
        }
        CP_COMMIT();
    };

    if (0 < niter) { load_stage(0, 0); }
    if (1 < niter) { load_stage(1, 1); }

    for (int i = 0; i < niter; i++) {
        if (i + 2 < niter) load_stage((i + 2) % STAGES, i + 2);
        if (i + 2 < niter)      { CP_WAIT2(); }
        else if (i + 1 < niter) { CP_WAIT1(); }
        else                    { CP_WAIT0(); }
        __syncthreads();

        const uint32_t* sA = smem + (i % STAGES) * STG_ENT;
        const uint32_t* sB = sA + A_ENT;
        const uint32_t* pa = sA + (wm * 64 + gid) * AE + tig;
        const uint32_t* pb = sB + tig * BE + wn * 32 + gid;

        #pragma unroll
        for (int s = 0; s < 2; s++) {           // two k16 steps per BK=32
            uint32_t bfr[4][2];
            #pragma unroll
            for (int ni = 0; ni < 4; ni++) {
                bfr[ni][0] = pb[(s * 8)     * BE + ni * 8];
                bfr[ni][1] = pb[(s * 8 + 4) * BE + ni * 8];
            }
            #pragma unroll
            for (int mi = 0; mi < 4; mi++) {
                const uint32_t* p = pa + mi * 16 * AE + s * 8;
                uint32_t a0 = p[0];
                uint32_t a1 = p[8 * AE];
                uint32_t a2 = p[4];
                uint32_t a3 = p[8 * AE + 4];
                #pragma unroll
                for (int ni = 0; ni < 4; ni++)
                    mma_f16(acc[mi][ni][0], acc[mi][ni][1], acc[mi][ni][2], acc[mi][ni][3],
                            a0, a1, a2, a3, bfr[ni][0], bfr[ni][1]);
            }
        }
        __syncthreads();
    }

    // ---------------- epilogue ----------------
    #pragma unroll
    for (int mi = 0; mi < 4; mi++) {
        #pragma unroll
        for (int half = 0; half < 2; half++) {
            const size_t r = (size_t)(row0 + wm * 64 + mi * 16 + gid + half * 8);
            #pragma unroll
            for (int ni = 0; ni < 4; ni++) {
                const int cc = col0 + wn * 32 + ni * 8 + tig * 2;
                float v0 = acc[mi][ni][half * 2 + 0] + bias[cc];
                float v1 = acc[mi][ni][half * 2 + 1] + bias[cc + 1];
                if (do_gelu) {
                    v0 = 0.5f * v0 * (1.f + erff(v0 * 0.70710678118654752f));
                    v1 = 0.5f * v1 * (1.f + erff(v1 * 0.70710678118654752f));
                }
                if (res) {
                    float2 rr = *(const float2*)&res[r * N + cc];
                    v0 += rr.x; v1 += rr.y;
                }
                if (out_half) {
                    *(__half2*)((__half*)Cv + r * N + cc) = __floats2half2_rn(v0, v1);
                } else {
                    *(float2*)((float*)Cv + r * N + cc) = make_float2(v0, v1);
                }
            }
        }
    }
}

// ---------------- fused double LayerNorm (fp16 outputs) ----------------
__global__ void ln_kernel(const float* __restrict__ x,
                          const float* __restrict__ aw, const float* __restrict__ ab,
                          const float* __restrict__ fw, const float* __restrict__ fb,
                          __half* __restrict__ nx, __half* __restrict__ f)
{
    int row = blockIdx.x;
    int tid = threadIdx.x;
    const float4* xr = (const float4*)(x + (size_t)row * Dz);
    float4 a = xr[tid];
    float4 b = xr[tid + 256];
    float s  = a.x + a.y + a.z + a.w + b.x + b.y + b.z + b.w;
    float ss = a.x*a.x + a.y*a.y + a.z*a.z + a.w*a.w
             + b.x*b.x + b.y*b.y + b.z*b.z + b.w*b.w;
    #pragma unroll
    for (int o = 16; o; o >>= 1) {
        s  += __shfl_xor_sync(0xffffffffu, s,  o);
        ss += __shfl_xor_sync(0xffffffffu, ss, o);
    }
    __shared__ float r1[8], r2[8];
    __shared__ float mv[2];
    int wid = tid >> 5;
    if ((tid & 31) == 0) { r1[wid] = s; r2[wid] = ss; }
    __syncthreads();
    if (tid == 0) {
        float S = 0.f, SS = 0.f;
        #pragma unroll
        for (int i = 0; i < 8; i++) { S += r1[i]; SS += r2[i]; }
        float m   = S * (1.f / Dz);
        float var = SS * (1.f / Dz) - m * m;
        mv[0] = m;
        mv[1] = rsqrtf(var + EPSF);
    }
    __syncthreads();
    float m = mv[0], r = mv[1];

    __half* nxr = nx + (size_t)row * Dz;
    __half* fr  = f  + (size_t)row * Dz;
    const float4* aw4 = (const float4*)aw;  const float4* ab4 = (const float4*)ab;
    const float4* fw4 = (const float4*)fw;  const float4* fb4 = (const float4*)fb;
    #pragma unroll
    for (int e = 0; e < 2; e++) {
        int slot = tid + e * 256;
        float4 v = (e == 0) ? a : b;
        float4 w1 = aw4[slot], b1 = ab4[slot], w2 = fw4[slot], b2 = fb4[slot];
        __half2 h0 = __floats2half2_rn((v.x - m) * r * w1.x + b1.x, (v.y - m) * r * w1.y + b1.y);
        __half2 h1 = __floats2half2_rn((v.z - m) * r * w1.z + b1.z, (v.w - m) * r * w1.w + b1.w);
        __half2 g0 = __floats2half2_rn((v.x - m) * r * w2.x + b2.x, (v.y - m) * r * w2.y + b2.y);
        __half2 g1 = __floats2half2_rn((v.z - m) * r * w2.z + b2.z, (v.w - m) * r * w2.w + b2.w);
        *(__half2*)(nxr + slot * 4)     = h0;
        *(__half2*)(nxr + slot * 4 + 2) = h1;
        *(__half2*)(fr  + slot * 4)     = g0;
        *(__half2*)(fr  + slot * 4 + 2) = g1;
    }
}

// ---------------- per-head RMS norm + RoPE + q scaling + tf32 round (q,k only) ----------------
__global__ void qkrope_kernel(float* __restrict__ qkv, const float* __restrict__ fc,
                              const float* __restrict__ qn_w, const float* __restrict__ kn_w)
{
    int blk   = blockIdx.x;
    int token = blk >> 4;
    int h     = blk & 15;
    int s     = token & (Sz - 1);
    int sel   = threadIdx.x >> 7;       // 0=q, 1=k
    int d     = threadIdx.x & 127;
    float* ptr = qkv + (size_t)token * (3 * Dz) + sel * Dz + h * HDz;
    float v = ptr[d];
    float ss = v * v;
    #pragma unroll
    for (int o = 16; o; o >>= 1) ss += __shfl_xor_sync(0xffffffffu, ss, o);
    __shared__ float red[8];
    __shared__ float rstd_s[2];
    int wid = threadIdx.x >> 5;
    if ((threadIdx.x & 31) == 0) red[wid] = ss;
    __syncthreads();
    if (d == 0) {
        float t = red[sel * 4] + red[sel * 4 + 1] + red[sel * 4 + 2] + red[sel * 4 + 3];
        rstd_s[sel] = rsqrtf(t * (1.f / HDz) + EPSF);
    }
    __syncthreads();
    float rstd = rstd_s[sel];
    float w = sel ? kn_w[d] : qn_w[d];
    float nv = v * rstd * w;
    if (d < RNz) {
        int j = d >> 1;
        float c  = fc[(s * 16 + j) * 2];
        float sn = fc[(s * 16 + j) * 2 + 1];
        float a = __shfl_sync(0xffffffffu, nv, j);
        float b = __shfl_sync(0xffffffffu, nv, j + 16);
        nv = (d & 1) ? (b * c + a * sn) : (a * c - b * sn);
    }
    if (sel == 0) nv *= SCALEF;
    ptr[d] = tf32v(nv);
}

// ======================= FA2-style windowed attention =======================
#define AT_CK 32
#define KSTR 132
#define VSTR 136
#define AT_K_OFF(buf) ((buf) * (AT_CK * KSTR))
#define AT_V_OFF(buf) (2 * AT_CK * KSTR + (buf) * (AT_CK * VSTR))
#define AT_SMEM_FLOATS (2 * AT_CK * KSTR + 2 * AT_CK * VSTR)   // 17152
#define AT_SMEM_BYTES  (AT_SMEM_FLOATS * 4)                     // 68608

__global__ __launch_bounds__(128, 2)
void attn_mma_kernel(const float* __restrict__ qkv, __half* __restrict__ y)
{
    extern __shared__ float sm[];
    const uint32_t sm0 = smem_u32(sm);
    const int tid  = threadIdx.x;
    const int wi   = tid >> 5;
    const int lane = tid & 31;
    const int gid  = lane >> 2;
    const int tig  = lane & 3;
    const int qb0  = (blockIdx.x & 31) << 6;
    const int h    = (blockIdx.x >> 5) & 15;
    const int b    = blockIdx.x >> 9;
    const int qw   = qb0 + wi * 16;

    uint32_t qf[16][4];
    {
        const float* q0 = qkv + (size_t)(b * Sz + qw + gid) * (3 * Dz) + h * HDz;
        const float* q1 = q0 + (size_t)8 * (3 * Dz);
        #pragma unroll
        for (int kg = 0; kg < 16; kg++) {
            qf[kg][0] = __float_as_uint(q0[kg * 8 + tig]);
            qf[kg][1] = __float_as_uint(q1[kg * 8 + tig]);
            qf[kg][2] = __float_as_uint(q0[kg * 8 + tig + 4]);
            qf[kg][3] = __float_as_uint(q1[kg * 8 + tig + 4]);
        }
    }

    float o[16][4];
    #pragma unroll
    for (int dt = 0; dt < 16; dt++)
        #pragma unroll
        for (int e = 0; e < 4; e++) o[dt][e] = 0.f;
    float m0 = -1e30f, m1 = -1e30f, l0 = 0.f, l1 = 0.f;

    int cs = qb0 - (WINz - 1); if (cs < 0) cs = 0;
    cs &= ~31;
    const int nc = ((qb0 + 63 - cs) >> 5) + 1;

    auto load_chunk = [&](int buf, int jc) {
        #pragma unroll
        for (int i = 0; i < 8; i++) {
            int fidx = i * 128 + tid;
            int row = fidx >> 5, c4 = fidx & 31;
            const float* gk = qkv + (size_t)(b * Sz + jc + row) * (3 * Dz) + Dz + h * HDz + c4 * 4;
            CP_ASYNC16(sm0 + (uint32_t)(AT_K_OFF(buf) + row * KSTR + c4 * 4) * 4, gk);
        }
        #pragma unroll
        for (int i = 0; i < 8; i++) {
            int fidx = i * 128 + tid;
            int row = fidx >> 5, c4 = fidx & 31;
            const float* gv = qkv + (size_t)(b * Sz + jc + row) * (3 * Dz) + 2 * Dz + h * HDz + c4 * 4;
            CP_ASYNC16(sm0 + (uint32_t)(AT_V_OFF(buf) + row * VSTR + c4 * 4) * 4, gv);
        }
        CP_COMMIT();
    };

    load_chunk(0, cs);

    for (int c = 0; c < nc; c++) {
        const int jc  = cs + c * 32;
        const int buf = c & 1;
        if (c + 1 < nc) { load_chunk((c + 1) & 1, jc + 32); CP_WAIT1(); }
        else            { CP_WAIT0(); }
        __syncthreads();

        const bool act = (jc <= qw + 15) && (jc + 31 >= qw - (WINz - 1));
        if (act) {
            const uint32_t* Ks = (const uint32_t*)(sm + AT_K_OFF(buf));
            const uint32_t* Vs = (const uint32_t*)(sm + AT_V_OFF(buf));

            float sc[4][4];
            #pragma unroll
            for (int ng = 0; ng < 4; ng++)
                #pragma unroll
                for (int e = 0; e < 4; e++) sc[ng][e] = 0.f;
            #pragma unroll
            for (int kg = 0; kg < 16; kg++) {
                #pragma unroll
                for (int ng = 0; ng < 4; ng++) {
                    const uint32_t* kp = Ks + (ng * 8 + gid) * KSTR + kg * 8 + tig;
                    mma_tf32(sc[ng][0], sc[ng][1], sc[ng][2], sc[ng][3],
                             qf[kg][0], qf[kg][1], qf[kg][2], qf[kg][3],
                             kp[0], kp[4]);
                }
            }

            const int q0r = qw + gid, q1r = qw + gid + 8;
            float smax0 = -1e30f, smax1 = -1e30f;
            #pragma unroll
            for (int ng = 0; ng < 4; ng++) {
                int j0 = jc + ng * 8 + tig * 2;
                smax0 = fmaxf(smax0, ((unsigned)(q0r - j0)     < 256u) ? sc[ng][0] : -1e30f);
                smax0 = fmaxf(smax0, ((unsigned)(q0r - j0 - 1) < 256u) ? sc[ng][1] : -1e30f);
                smax1 = fmaxf(smax1, ((unsigned)(q1r - j0)     < 256u) ? sc[ng][2] : -1e30f);
                smax1 = fmaxf(smax1, ((unsigned)(q1r - j0 - 1) < 256u) ? sc[ng][3] : -1e30f);
            }
            smax0 = fmaxf(smax0, __shfl_xor_sync(0xffffffffu, smax0, 1));
            smax0 = fmaxf(smax0, __shfl_xor_sync(0xffffffffu, smax0, 2));
            smax1 = fmaxf(smax1, __shfl_xor_sync(0xffffffffu, smax1, 1));
            smax1 = fmaxf(smax1, __shfl_xor_sync(0xffffffffu, smax1, 2));
            float m0n = fmaxf(m0, smax0), m1n = fmaxf(m1, smax1);
            float cr0 = __expf(m0 - m0n), cr1 = __expf(m1 - m1n);
            m0 = m0n; m1 = m1n;

            float ps0 = 0.f, ps1 = 0.f;
            #pragma unroll
            for (int ng = 0; ng < 4; ng++) {
                int j0 = jc + ng * 8 + tig * 2;
                float e;
                e = ((unsigned)(q0r - j0)     < 256u) ? __expf(sc[ng][0] - m0) : 0.f;
                sc[ng][0] = e; ps0 += e;
                e = ((unsigned)(q0r - j0 - 1) < 256u) ? __expf(sc[ng][1] - m0) : 0.f;
                sc[ng][1] = e; ps0 += e;
                e = ((unsigned)(q1r - j0)     < 256u) ? __expf(sc[ng][2] - m1) : 0.f;
                sc[ng][2] = e; ps1 += e;
                e = ((unsigned)(q1r - j0 - 1) < 256u) ? __expf(sc[ng][3] - m1) : 0.f;
                sc[ng][3] = e; ps1 += e;
            }
            ps0 += __shfl_xor_sync(0xffffffffu, ps0, 1);
            ps0 += __shfl_xor_sync(0xffffffffu, ps0, 2);
            ps1 += __shfl_xor_sync(0xffffffffu, ps1, 1);
            ps1 += __shfl_xor_sync(0xffffffffu, ps1, 2);
            l0 = l0 * cr0 + ps0;
            l1 = l1 * cr1 + ps1;

            #pragma unroll
            for (int dt = 0; dt < 16; dt++) {
                o[dt][0] *= cr0; o[dt][1] *= cr0;
                o[dt][2] *= cr1; o[dt][3] *= cr1;
            }

            uint32_t af[4][4];
            const int src  = (lane & ~3) | (tig >> 1);
            const int src2 = src + 2;
            #pragma unroll
            for (int ng = 0; ng < 4; ng++) {
                float v0 = __shfl_sync(0xffffffffu, sc[ng][0], src);
                float v1 = __shfl_sync(0xffffffffu, sc[ng][1], src);
                float v2 = __shfl_sync(0xffffffffu, sc[ng][2], src);
                float v3 = __shfl_sync(0xffffffffu, sc[ng][3], src);
                float w0 = __shfl_sync(0xffffffffu, sc[ng][0], src2);
                float w1 = __shfl_sync(0xffffffffu, sc[ng][1], src2);
                float w2 = __shfl_sync(0xffffffffu, sc[ng][2], src2);
                float w3 = __shfl_sync(0xffffffffu, sc[ng][3], src2);
                af[ng][0] = f2tf32((tig & 1) ? v1 : v0);
                af[ng][1] = f2tf32((tig & 1) ? v3 : v2);
                af[ng][2] = f2tf32((tig & 1) ? w1 : w0);
                af[ng][3] = f2tf32((tig & 1) ? w3 : w2);
            }

            #pragma unroll
            for (int dt = 0; dt < 16; dt++) {
                #pragma unroll
                for (int ng = 0; ng < 4; ng++) {
                    const uint32_t* vp = Vs + (ng * 8 + tig) * VSTR + dt * 8 + gid;
                    mma_tf32(o[dt][0], o[dt][1], o[dt][2], o[dt][3],
                             af[ng][0], af[ng][1], af[ng][2], af[ng][3],
                             vp[0], vp[4 * VSTR]);
                }
            }
        }
        __syncthreads();
    }

    const float i0 = 1.f / l0, i1 = 1.f / l1;
    __half* y0 = y + (size_t)(b * Sz + qw + gid) * Dz + h * HDz;
    __half* y1 = y0 + (size_t)8 * Dz;
    #pragma unroll
    for (int dt = 0; dt < 16; dt++) {
        *(__half2*)(y0 + dt * 8 + tig * 2) = __floats2half2_rn(o[dt][0] * i0, o[dt][1] * i0);
        *(__half2*)(y1 + dt * 8 + tig * 2) = __floats2half2_rn(o[dt][2] * i1, o[dt][3] * i1);
    }
}

// ---------------- launch ----------------
extern "C" void kernel_launch(void* const* d_in, const int* in_sizes, int n_in,
                              void* d_out, int out_size)
{
    const float* x      = (const float*)d_in[0];
    const float* fc     = (const float*)d_in[1];
    // d_in[2] = mask (implicit: causal sliding window of 256)
    const float* wqkv_w = (const float*)d_in[3];
    const float* wqkv_b = (const float*)d_in[4];
    const float* wo_w   = (const float*)d_in[5];
    const float* wo_b   = (const float*)d_in[6];
    const float* qn_w   = (const float*)d_in[7];
    const float* kn_w   = (const float*)d_in[8];
    const float* aln_w  = (const float*)d_in[9];
    const float* aln_b  = (const float*)d_in[10];
    const float* fln_w  = (const float*)d_in[11];
    const float* fln_b  = (const float*)d_in[12];
    const float* w1_w   = (const float*)d_in[13];
    const float* w1_b   = (const float*)d_in[14];
    const float* w2_w   = (const float*)d_in[15];
    const float* w2_b   = (const float*)d_in[16];
    float* out = (float*)d_out;

    __half *nx, *f, *y, *ffn;
    float *qkv, *h, *ffo;
    __half2 *wqkvH, *woH, *w1H, *w2H;
    cudaGetSymbolAddress((void**)&nx,    g_nx);
    cudaGetSymbolAddress((void**)&f,     g_f);
    cudaGetSymbolAddress((void**)&qkv,   g_qkv);
    cudaGetSymbolAddress((void**)&y,     g_y);
    cudaGetSymbolAddress((void**)&h,     g_h);
    cudaGetSymbolAddress((void**)&ffn,   g_ffn);
    cudaGetSymbolAddress((void**)&ffo,   g_ffo);
    cudaGetSymbolAddress((void**)&wqkvH, g_wqkvH);
    cudaGetSymbolAddress((void**)&woH,   g_woH);
    cudaGetSymbolAddress((void**)&w1H,   g_w1H);
    cudaGetSymbolAddress((void**)&w2H,   g_w2H);

    static int init_done = 0;
    static cudaStream_t s2;
    static cudaEvent_t evL, evW, ev1;
    if (!init_done) {
        cudaFuncSetAttribute(tc_gemm_kernel,
                             cudaFuncAttributeMaxDynamicSharedMemorySize, SM_TOTAL);
        cudaFuncSetAttribute(attn_mma_kernel,
                             cudaFuncAttributeMaxDynamicSharedMemorySize, AT_SMEM_BYTES);
        cudaStreamCreateWithFlags(&s2, cudaStreamNonBlocking);
        cudaEventCreateWithFlags(&evL, cudaEventDisableTiming);
        cudaEventCreateWithFlags(&evW, cudaEventDisableTiming);
        cudaEventCreateWithFlags(&ev1, cudaEventDisableTiming);
        init_done = 1;
    }

    // ---- stream 0: LN first (first captured node), then fork to s2 ----
    ln_kernel<<<TOK, 256>>>(x, aln_w, aln_b, fln_w, fln_b, nx, f);
    cudaEventRecord(evL, 0);

    // ---- stream s2: merged weight pack -> evW, then FFN tower -> ev1 ----
    cudaStreamWaitEvent(s2, evL, 0);
    wconv_all_kernel<<<16384, 256, 0, s2>>>(wqkv_w, wo_w, w1_w, w2_w,
                                            wqkvH, woH, w1H, w2H);
    cudaEventRecord(evW, s2);
    tc_gemm_kernel<<<dim3(FFz / BN, TOK / BM), 256, SM_TOTAL, s2>>>(
        f, w1H, w1_b, nullptr, ffn, TOK, FFz, Dz, 1, 1);
    tc_gemm_kernel<<<dim3(Dz / BN, TOK / BM), 256, SM_TOTAL, s2>>>(
        ffn, w2H, w2_b, nullptr, ffo, TOK, Dz, FFz, 0, 0);
    cudaEventRecord(ev1, s2);

    // ---- stream 0: attention chain (QKV needs wqkvH -> wait evW only) ----
    cudaStreamWaitEvent(0, evW, 0);
    tc_gemm_kernel<<<dim3(3 * Dz / BN, TOK / BM), 256, SM_TOTAL>>>(
        nx, wqkvH, wqkv_b, nullptr, qkv, TOK, 3 * Dz, Dz, 0, 0);
    qkrope_kernel<<<TOK * Hz, 256>>>(qkv, fc, qn_w, kn_w);
    attn_mma_kernel<<<Bz * Hz * (Sz / 64), 128, AT_SMEM_BYTES>>>(qkv, y);
    tc_gemm_kernel<<<dim3(Dz / BN, TOK / BM), 256, SM_TOTAL>>>(
        y, woH, wo_b, x, h, TOK, Dz, Dz, 0, 0);

    // ---- join: out = h + ffo ----
    cudaStreamWaitEvent(0, ev1, 0);
    add_kernel<<<(TOK * Dz / 4) / 256, 256>>>(h, ffo, out);
}